// round 7
// baseline (speedup 1.0000x reference)
#include <cuda_runtime.h>
#include <cstdint>

#define NMAX 100000
#define H 128

// Scratch (allocation-free: __device__ globals, 0.8 MB total)
__device__ int   g_deg[NMAX];
__device__ float g_dinv[NMAX];

// ---------------------------------------------------------------------------
// init: zero output accumulator, deg = 1 (self-loop)
// ---------------------------------------------------------------------------
__global__ void k_init(float4* __restrict__ out4, int n) {
    int idx = blockIdx.x * blockDim.x + threadIdx.x;
    int total = n * (H / 4);
    if (idx < total) out4[idx] = make_float4(0.f, 0.f, 0.f, 0.f);
    if (idx < n) g_deg[idx] = 1;
}

// ---------------------------------------------------------------------------
// degree: in-degree count over dst (int32 indices!)
// ---------------------------------------------------------------------------
__global__ void k_deg(const int* __restrict__ dst, int E) {
    int e = blockIdx.x * blockDim.x + threadIdx.x;
    if (e < E) atomicAdd(&g_deg[dst[e]], 1);
}

__global__ void k_dinv(int n) {
    int i = blockIdx.x * blockDim.x + threadIdx.x;
    if (i < n) g_dinv[i] = rsqrtf((float)g_deg[i]);
}

// ---------------------------------------------------------------------------
// Edge scatter on RAW features: one warp per edge.
// out[dst] += x[src] * (dinv[src]*dinv[dst]); float4 atomicAdd (RED.128).
// ---------------------------------------------------------------------------
__global__ void k_scatter(const int* __restrict__ src,
                          const int* __restrict__ dst,
                          const float* __restrict__ x,
                          float* __restrict__ out, int E) {
    int t    = blockIdx.x * blockDim.x + threadIdx.x;
    int e    = t >> 5;
    int lane = t & 31;
    if (e >= E) return;

    int s = src[e];
    int d = dst[e];
    float norm = g_dinv[s] * g_dinv[d];

    float4 v = ((const float4*)x)[s * 32 + lane];
    v.x *= norm; v.y *= norm; v.z *= norm; v.w *= norm;
    atomicAdd((float4*)(out + (size_t)d * H) + lane, v);
}

// ---------------------------------------------------------------------------
// Fused in-place GEMM: out = (agg + x*dinv^2) @ W^T + b, then PReLU.
// Block tile 64 rows x 128 cols, K tiled by 32, thread tile 4x8.
// Static shared only (27.6 KB). Each block loads its own 64-row input tile
// into smem before writing those same rows -> in-place is safe.
// ---------------------------------------------------------------------------
#define KT 32
#define KP 36   // padded K-tile stride (floats)

__global__ __launch_bounds__(256)
void k_gemm(const float* __restrict__ x, const float* __restrict__ W,
            const float* __restrict__ b, const float* __restrict__ prelu_a,
            float* __restrict__ out, int n) {
    __shared__ float xs[64 * KP];    // input tile (agg + self-loop)
    __shared__ float Ws[128 * KP];

    int tid  = threadIdx.x;
    int row0 = blockIdx.x * 64;

    int tx = tid & 15, ty = tid >> 4;
    int r0 = ty * 4;   // 4 rows per thread
    int c0 = tx * 8;   // 8 cols per thread

    float acc[4][8];
#pragma unroll
    for (int i = 0; i < 4; i++)
#pragma unroll
        for (int j = 0; j < 8; j++) acc[i][j] = 0.f;

    for (int k0 = 0; k0 < 128; k0 += KT) {
        // W tile: 128 cols x 32 k = 1024 float4s / 256 threads.
#pragma unroll
        for (int it = 0; it < 4; it++) {
            int i = tid + it * 256;
            int c = i >> 3, k4 = i & 7;
            float4 v = ((const float4*)W)[c * 32 + (k0 >> 2) + k4];
            *(float4*)&Ws[c * KP + k4 * 4] = v;
        }
        // Input tile: agg(out) + x * dinv^2 (self-loop fused here).
#pragma unroll
        for (int it = 0; it < 2; it++) {
            int i = tid + it * 256;
            int r = i >> 3, k4 = i & 7;
            int gr = row0 + r;
            float4 v = make_float4(0.f, 0.f, 0.f, 0.f);
            if (gr < n) {
                float di = g_dinv[gr];
                float sl = di * di;
                float4 ag = ((const float4*)out)[gr * 32 + (k0 >> 2) + k4];
                float4 xv = ((const float4*)x)[gr * 32 + (k0 >> 2) + k4];
                v.x = ag.x + xv.x * sl;
                v.y = ag.y + xv.y * sl;
                v.z = ag.z + xv.z * sl;
                v.w = ag.w + xv.w * sl;
            }
            *(float4*)&xs[r * KP + k4 * 4] = v;
        }
        __syncthreads();

#pragma unroll
        for (int k = 0; k < KT; k += 4) {
            float4 xv[4], wv[8];
#pragma unroll
            for (int i = 0; i < 4; i++) xv[i] = *(float4*)&xs[(r0 + i) * KP + k];
#pragma unroll
            for (int j = 0; j < 8; j++) wv[j] = *(float4*)&Ws[(c0 + j) * KP + k];
#pragma unroll
            for (int i = 0; i < 4; i++) {
#pragma unroll
                for (int j = 0; j < 8; j++) {
                    acc[i][j] += xv[i].x * wv[j].x;
                    acc[i][j] += xv[i].y * wv[j].y;
                    acc[i][j] += xv[i].z * wv[j].z;
                    acc[i][j] += xv[i].w * wv[j].w;
                }
            }
        }
        __syncthreads();
    }

    // Epilogue: bias + PReLU, write back in place.
    float a = prelu_a[0];
    float bb[8];
#pragma unroll
    for (int j = 0; j < 8; j++) bb[j] = b[c0 + j];

#pragma unroll
    for (int i = 0; i < 4; i++) {
        int r = row0 + r0 + i;
        if (r < n) {
            float vals[8];
#pragma unroll
            for (int j = 0; j < 8; j++) {
                float v = acc[i][j] + bb[j];
                vals[j] = v >= 0.f ? v : a * v;
            }
            float4* op = (float4*)out + r * 32 + (c0 >> 2);
            op[0] = make_float4(vals[0], vals[1], vals[2], vals[3]);
            op[1] = make_float4(vals[4], vals[5], vals[6], vals[7]);
        }
    }
}

// ---------------------------------------------------------------------------
extern "C" void kernel_launch(void* const* d_in, const int* in_sizes, int n_in,
                              void* d_out, int out_size) {
    const float* x  = (const float*)d_in[0];
    const int*   ei = (const int*)d_in[1];      // int32! (JAX x64 disabled)
    const float* W  = (const float*)d_in[2];
    const float* b  = (const float*)d_in[3];
    const float* pa = (const float*)d_in[4];
    float* out = (float*)d_out;

    int n = in_sizes[0] / H;          // 100000
    int E = in_sizes[1] / 2;          // 1600000
    const int* src = ei;
    const int* dst = ei + E;

    int tot4 = n * 32;
    k_init<<<(tot4 + 255) / 256, 256>>>((float4*)out, n);
    k_deg<<<(E + 255) / 256, 256>>>(dst, E);
    k_dinv<<<(n + 255) / 256, 256>>>(n);
    k_scatter<<<(int)(((long long)E * 32 + 255) / 256), 256>>>(src, dst, x, out, E);
    k_gemm<<<(n + 63) / 64, 256>>>(x, W, b, pa, out, n);
}

// round 8
// speedup vs baseline: 1.6427x; 1.6427x over previous
#include <cuda_runtime.h>
#include <cstdint>

#define NMAX 100000
#define H 128

// Scratch (allocation-free: __device__ globals, 0.8 MB total)
__device__ int   g_deg[NMAX];
__device__ float g_dinv[NMAX];

// ---------------------------------------------------------------------------
// init: zero output accumulator, deg = 1 (self-loop)
// ---------------------------------------------------------------------------
__global__ void k_init(float4* __restrict__ out4, int n) {
    int idx = blockIdx.x * blockDim.x + threadIdx.x;
    int total = n * (H / 4);
    if (idx < total) out4[idx] = make_float4(0.f, 0.f, 0.f, 0.f);
    if (idx < n) g_deg[idx] = 1;
}

// ---------------------------------------------------------------------------
// degree: in-degree count over dst (int32 indices)
// ---------------------------------------------------------------------------
__global__ void k_deg(const int* __restrict__ dst, int E) {
    int e = blockIdx.x * blockDim.x + threadIdx.x;
    if (e < E) atomicAdd(&g_deg[dst[e]], 1);
}

__global__ void k_dinv(int n) {
    int i = blockIdx.x * blockDim.x + threadIdx.x;
    if (i < n) g_dinv[i] = rsqrtf((float)g_deg[i]);
}

// ---------------------------------------------------------------------------
// Edge scatter on RAW features: one warp per edge.
// out[dst] += x[src] * (dinv[src]*dinv[dst]); float4 atomicAdd (RED.128).
// ---------------------------------------------------------------------------
__global__ void k_scatter(const int* __restrict__ src,
                          const int* __restrict__ dst,
                          const float* __restrict__ x,
                          float* __restrict__ out, int E) {
    int t    = blockIdx.x * blockDim.x + threadIdx.x;
    int e    = t >> 5;
    int lane = t & 31;
    if (e >= E) return;

    int s = src[e];
    int d = dst[e];
    float norm = g_dinv[s] * g_dinv[d];

    float4 v = ((const float4*)x)[s * 32 + lane];
    v.x *= norm; v.y *= norm; v.z *= norm; v.w *= norm;
    atomicAdd((float4*)(out + (size_t)d * H) + lane, v);
}

// ---------------------------------------------------------------------------
// Fused in-place GEMM: out = (agg + x*dinv^2) @ W^T + b, then PReLU.
// Block tile 64 rows x 128 cols, K tiled by 32, thread tile 4x8.
// Smem tiles stored K-MAJOR: all lanes of a warp read the same k, spread
// across c/r -> conflict-free LDS.128 on the hot path (the c-major layout
// had a 16-way conflict: lane stride 8*KP floats = 0 mod 32 banks).
// ---------------------------------------------------------------------------
#define KT 32
#define WR 132   // Ws row stride (floats), k-major rows of 128 cols + pad
#define XR 68    // xs row stride (floats), k-major rows of 64 rows + pad

__global__ __launch_bounds__(256)
void k_gemm(const float* __restrict__ x, const float* __restrict__ W,
            const float* __restrict__ b, const float* __restrict__ prelu_a,
            float* __restrict__ out, int n) {
    __shared__ float Ws[KT * WR];   // Ws[k][c]  16.9 KB
    __shared__ float xs[KT * XR];   // xs[k][r]   8.7 KB

    int tid  = threadIdx.x;
    int row0 = blockIdx.x * 64;

    int tx = tid & 15, ty = tid >> 4;
    int r0 = ty * 4;   // 4 rows per thread
    int c0 = tx * 8;   // 8 cols per thread

    float acc[4][8];
#pragma unroll
    for (int i = 0; i < 4; i++)
#pragma unroll
        for (int j = 0; j < 8; j++) acc[i][j] = 0.f;

    for (int k0 = 0; k0 < 128; k0 += KT) {
        // W tile: load W[c][k0+4*k4 .. +3] as float4, store transposed
        // into Ws[k][c]. 1024 float4s / 256 threads.
#pragma unroll
        for (int it = 0; it < 4; it++) {
            int i = tid + it * 256;
            int c = i >> 3, k4 = i & 7;
            float4 v = ((const float4*)W)[c * 32 + (k0 >> 2) + k4];
            Ws[(k4 * 4 + 0) * WR + c] = v.x;
            Ws[(k4 * 4 + 1) * WR + c] = v.y;
            Ws[(k4 * 4 + 2) * WR + c] = v.z;
            Ws[(k4 * 4 + 3) * WR + c] = v.w;
        }
        // Input tile: (agg + x*dinv^2), transposed into xs[k][r].
#pragma unroll
        for (int it = 0; it < 2; it++) {
            int i = tid + it * 256;
            int r = i >> 3, k4 = i & 7;
            int gr = row0 + r;
            float4 v = make_float4(0.f, 0.f, 0.f, 0.f);
            if (gr < n) {
                float di = g_dinv[gr];
                float sl = di * di;
                float4 ag = ((const float4*)out)[gr * 32 + (k0 >> 2) + k4];
                float4 xv = ((const float4*)x)[gr * 32 + (k0 >> 2) + k4];
                v.x = ag.x + xv.x * sl;
                v.y = ag.y + xv.y * sl;
                v.z = ag.z + xv.z * sl;
                v.w = ag.w + xv.w * sl;
            }
            xs[(k4 * 4 + 0) * XR + r] = v.x;
            xs[(k4 * 4 + 1) * XR + r] = v.y;
            xs[(k4 * 4 + 2) * XR + r] = v.z;
            xs[(k4 * 4 + 3) * XR + r] = v.w;
        }
        __syncthreads();

#pragma unroll
        for (int k = 0; k < KT; k++) {
            float4 xv = *(const float4*)&xs[k * XR + r0];
            float4 w0 = *(const float4*)&Ws[k * WR + c0];
            float4 w1 = *(const float4*)&Ws[k * WR + c0 + 4];
            float xr[4] = {xv.x, xv.y, xv.z, xv.w};
            float wc[8] = {w0.x, w0.y, w0.z, w0.w, w1.x, w1.y, w1.z, w1.w};
#pragma unroll
            for (int i = 0; i < 4; i++)
#pragma unroll
                for (int j = 0; j < 8; j++)
                    acc[i][j] += xr[i] * wc[j];
        }
        __syncthreads();
    }

    // Epilogue: bias + PReLU, write back in place.
    float a = prelu_a[0];
    float bb[8];
#pragma unroll
    for (int j = 0; j < 8; j++) bb[j] = b[c0 + j];

#pragma unroll
    for (int i = 0; i < 4; i++) {
        int r = row0 + r0 + i;
        if (r < n) {
            float vals[8];
#pragma unroll
            for (int j = 0; j < 8; j++) {
                float v = acc[i][j] + bb[j];
                vals[j] = v >= 0.f ? v : a * v;
            }
            float4* op = (float4*)out + r * 32 + (c0 >> 2);
            op[0] = make_float4(vals[0], vals[1], vals[2], vals[3]);
            op[1] = make_float4(vals[4], vals[5], vals[6], vals[7]);
        }
    }
}

// ---------------------------------------------------------------------------
extern "C" void kernel_launch(void* const* d_in, const int* in_sizes, int n_in,
                              void* d_out, int out_size) {
    const float* x  = (const float*)d_in[0];
    const int*   ei = (const int*)d_in[1];      // int32 (JAX x64 disabled)
    const float* W  = (const float*)d_in[2];
    const float* b  = (const float*)d_in[3];
    const float* pa = (const float*)d_in[4];
    float* out = (float*)d_out;

    int n = in_sizes[0] / H;          // 100000
    int E = in_sizes[1] / 2;          // 1600000
    const int* src = ei;
    const int* dst = ei + E;

    int tot4 = n * 32;
    k_init<<<(tot4 + 255) / 256, 256>>>((float4*)out, n);
    k_deg<<<(E + 255) / 256, 256>>>(dst, E);
    k_dinv<<<(n + 255) / 256, 256>>>(n);
    k_scatter<<<(int)(((long long)E * 32 + 255) / 256), 256>>>(src, dst, x, out, E);
    k_gemm<<<(n + 63) / 64, 256>>>(x, W, b, pa, out, n);
}

// round 9
// speedup vs baseline: 2.3811x; 1.4495x over previous
#include <cuda_runtime.h>
#include <cstdint>

#define NMAX 100000
#define EMAX 1600000
#define H 128
#define NB_SCAN 98            // ceil(NMAX/1024)

// Scratch (allocation-free __device__ globals, ~8 MB)
__device__ int   g_cnt[NMAX];          // edge in-degree (no self-loop)
__device__ int   g_part[NMAX];         // block-local exclusive scan
__device__ int   g_bsum[128];          // per-block sums
__device__ int   g_boff[128];          // scanned block offsets
__device__ int   g_rowstart[NMAX + 1]; // CSR row starts
__device__ int   g_cursor[NMAX];       // fill cursors
__device__ float g_dinv[NMAX];
__device__ int   g_esrc[EMAX];         // src indices sorted by dst

// ---------------------------------------------------------------------------
__global__ void k_zero(int n) {
    int i = blockIdx.x * blockDim.x + threadIdx.x;
    if (i < n) g_cnt[i] = 0;
}

__global__ void k_deg(const int* __restrict__ dst, int E) {
    int e = blockIdx.x * blockDim.x + threadIdx.x;
    if (e < E) atomicAdd(&g_cnt[dst[e]], 1);
}

// ---------------------------------------------------------------------------
// 3-phase exclusive scan over g_cnt -> g_rowstart (+ cursor, dinv)
// ---------------------------------------------------------------------------
__global__ __launch_bounds__(1024)
void k_scanA(int n) {
    __shared__ int sm[1024];
    int t = threadIdx.x;
    int i = blockIdx.x * 1024 + t;
    int v = (i < n) ? g_cnt[i] : 0;
    sm[t] = v;
    __syncthreads();
#pragma unroll
    for (int off = 1; off < 1024; off <<= 1) {
        int u = (t >= off) ? sm[t - off] : 0;
        __syncthreads();
        sm[t] += u;
        __syncthreads();
    }
    if (i < n) g_part[i] = sm[t] - v;          // exclusive
    if (t == 1023) g_bsum[blockIdx.x] = sm[t]; // block total
}

__global__ __launch_bounds__(128)
void k_scanB() {
    __shared__ int sm[128];
    int t = threadIdx.x;
    int v = (t < NB_SCAN) ? g_bsum[t] : 0;
    sm[t] = v;
    __syncthreads();
#pragma unroll
    for (int off = 1; off < 128; off <<= 1) {
        int u = (t >= off) ? sm[t - off] : 0;
        __syncthreads();
        sm[t] += u;
        __syncthreads();
    }
    g_boff[t] = sm[t] - v;                     // exclusive
}

__global__ void k_scanC(int n, int E) {
    int i = blockIdx.x * blockDim.x + threadIdx.x;
    if (i < n) {
        int rs = g_part[i] + g_boff[i >> 10];
        g_rowstart[i] = rs;
        g_cursor[i]   = rs;
        g_dinv[i]     = rsqrtf((float)(g_cnt[i] + 1));  // +1 self-loop
    }
    if (i == 0) g_rowstart[n] = E;
}

// ---------------------------------------------------------------------------
// Counting-sort fill: g_esrc grouped by dst
// ---------------------------------------------------------------------------
__global__ void k_fill(const int* __restrict__ src,
                       const int* __restrict__ dst, int E) {
    int e = blockIdx.x * blockDim.x + threadIdx.x;
    if (e < E) {
        int pos = atomicAdd(&g_cursor[dst[e]], 1);
        g_esrc[pos] = src[e];
    }
}

// ---------------------------------------------------------------------------
// Gather: one warp per dst node. acc[lane] covers 4 features (float4).
// Chunked: 32 edge indices loaded coalesced per chunk, broadcast via shfl;
// x-row loads independent across edges -> high MLP, no atomics.
// ---------------------------------------------------------------------------
__global__ __launch_bounds__(256)
void k_gather(const float4* __restrict__ x4, float4* __restrict__ out4, int n) {
    int w    = (blockIdx.x * blockDim.x + threadIdx.x) >> 5;
    int lane = threadIdx.x & 31;
    if (w >= n) return;

    int beg = g_rowstart[w];
    int end = g_rowstart[w + 1];
    float dd = g_dinv[w];

    float4 acc = make_float4(0.f, 0.f, 0.f, 0.f);
    for (int j0 = beg; j0 < end; j0 += 32) {
        int jn = min(32, end - j0);
        int   s  = 0;
        float ds = 0.f;
        if (lane < jn) {
            s  = g_esrc[j0 + lane];
            ds = g_dinv[s];
        }
#pragma unroll 4
        for (int t = 0; t < jn; t++) {
            int   ss = __shfl_sync(0xffffffffu, s, t);
            float nm = __shfl_sync(0xffffffffu, ds, t) * dd;
            float4 v = __ldg(&x4[ss * 32 + lane]);
            acc.x += v.x * nm;
            acc.y += v.y * nm;
            acc.z += v.z * nm;
            acc.w += v.w * nm;
        }
    }
    out4[w * 32 + lane] = acc;   // plain store, no init needed
}

// ---------------------------------------------------------------------------
// Fused in-place GEMM: out = (agg + x*dinv^2) @ W^T + b, then PReLU.
// K-major smem tiles (conflict-free), 64x128 block tile, 4x8 thread tile.
// ---------------------------------------------------------------------------
#define KT 32
#define WR 132
#define XR 68

__global__ __launch_bounds__(256)
void k_gemm(const float* __restrict__ x, const float* __restrict__ W,
            const float* __restrict__ b, const float* __restrict__ prelu_a,
            float* __restrict__ out, int n) {
    __shared__ float Ws[KT * WR];
    __shared__ float xs[KT * XR];

    int tid  = threadIdx.x;
    int row0 = blockIdx.x * 64;

    int tx = tid & 15, ty = tid >> 4;
    int r0 = ty * 4;
    int c0 = tx * 8;

    float acc[4][8];
#pragma unroll
    for (int i = 0; i < 4; i++)
#pragma unroll
        for (int j = 0; j < 8; j++) acc[i][j] = 0.f;

    for (int k0 = 0; k0 < 128; k0 += KT) {
#pragma unroll
        for (int it = 0; it < 4; it++) {
            int i = tid + it * 256;
            int c = i >> 3, k4 = i & 7;
            float4 v = ((const float4*)W)[c * 32 + (k0 >> 2) + k4];
            Ws[(k4 * 4 + 0) * WR + c] = v.x;
            Ws[(k4 * 4 + 1) * WR + c] = v.y;
            Ws[(k4 * 4 + 2) * WR + c] = v.z;
            Ws[(k4 * 4 + 3) * WR + c] = v.w;
        }
#pragma unroll
        for (int it = 0; it < 2; it++) {
            int i = tid + it * 256;
            int r = i >> 3, k4 = i & 7;
            int gr = row0 + r;
            float4 v = make_float4(0.f, 0.f, 0.f, 0.f);
            if (gr < n) {
                float di = g_dinv[gr];
                float sl = di * di;
                float4 ag = ((const float4*)out)[gr * 32 + (k0 >> 2) + k4];
                float4 xv = ((const float4*)x)[gr * 32 + (k0 >> 2) + k4];
                v.x = ag.x + xv.x * sl;
                v.y = ag.y + xv.y * sl;
                v.z = ag.z + xv.z * sl;
                v.w = ag.w + xv.w * sl;
            }
            xs[(k4 * 4 + 0) * XR + r] = v.x;
            xs[(k4 * 4 + 1) * XR + r] = v.y;
            xs[(k4 * 4 + 2) * XR + r] = v.z;
            xs[(k4 * 4 + 3) * XR + r] = v.w;
        }
        __syncthreads();

#pragma unroll
        for (int k = 0; k < KT; k++) {
            float4 xv = *(const float4*)&xs[k * XR + r0];
            float4 w0 = *(const float4*)&Ws[k * WR + c0];
            float4 w1 = *(const float4*)&Ws[k * WR + c0 + 4];
            float xr[4] = {xv.x, xv.y, xv.z, xv.w};
            float wc[8] = {w0.x, w0.y, w0.z, w0.w, w1.x, w1.y, w1.z, w1.w};
#pragma unroll
            for (int i = 0; i < 4; i++)
#pragma unroll
                for (int j = 0; j < 8; j++)
                    acc[i][j] += xr[i] * wc[j];
        }
        __syncthreads();
    }

    float a = prelu_a[0];
    float bb[8];
#pragma unroll
    for (int j = 0; j < 8; j++) bb[j] = b[c0 + j];

#pragma unroll
    for (int i = 0; i < 4; i++) {
        int r = row0 + r0 + i;
        if (r < n) {
            float vals[8];
#pragma unroll
            for (int j = 0; j < 8; j++) {
                float v = acc[i][j] + bb[j];
                vals[j] = v >= 0.f ? v : a * v;
            }
            float4* op = (float4*)out + r * 32 + (c0 >> 2);
            op[0] = make_float4(vals[0], vals[1], vals[2], vals[3]);
            op[1] = make_float4(vals[4], vals[5], vals[6], vals[7]);
        }
    }
}

// ---------------------------------------------------------------------------
extern "C" void kernel_launch(void* const* d_in, const int* in_sizes, int n_in,
                              void* d_out, int out_size) {
    const float* x  = (const float*)d_in[0];
    const int*   ei = (const int*)d_in[1];      // int32 (JAX x64 disabled)
    const float* W  = (const float*)d_in[2];
    const float* b  = (const float*)d_in[3];
    const float* pa = (const float*)d_in[4];
    float* out = (float*)d_out;

    int n = in_sizes[0] / H;          // 100000
    int E = in_sizes[1] / 2;          // 1600000
    if (E > EMAX) E = EMAX;
    const int* src = ei;
    const int* dst = ei + E;

    k_zero <<<(n + 255) / 256, 256>>>(n);
    k_deg  <<<(E + 255) / 256, 256>>>(dst, E);
    k_scanA<<<NB_SCAN, 1024>>>(n);
    k_scanB<<<1, 128>>>();
    k_scanC<<<(n + 255) / 256, 256>>>(n, E);
    k_fill <<<(E + 255) / 256, 256>>>(src, dst, E);
    k_gather<<<(int)(((long long)n * 32 + 255) / 256), 256>>>(
        (const float4*)x, (float4*)out, n);
    k_gemm <<<(n + 63) / 64, 256>>>(x, W, b, pa, out, n);
}

// round 10
// speedup vs baseline: 2.4743x; 1.0391x over previous
#include <cuda_runtime.h>
#include <cstdint>

#define NMAX 100000
#define EMAX 1600000
#define H 128
#define NB_SCAN 98            // ceil(NMAX/1024)

// Scratch (allocation-free __device__ globals, ~8 MB)
__device__ int   g_cnt[NMAX];          // edge in-degree (no self-loop)
__device__ int   g_part[NMAX];         // block-local exclusive scan
__device__ int   g_bsum[128];          // per-block sums
__device__ int   g_boff[128];          // scanned block offsets
__device__ int   g_rowstart[NMAX + 1]; // CSR row starts
__device__ int   g_cursor[NMAX];       // fill cursors
__device__ float g_dinv[NMAX];
__device__ int   g_esrc[EMAX];         // src indices sorted by dst

// ---------------------------------------------------------------------------
__global__ void k_zero(int n) {
    int i = blockIdx.x * blockDim.x + threadIdx.x;
    if (i < n) g_cnt[i] = 0;
}

__global__ void k_deg(const int* __restrict__ dst, int E) {
    int e = blockIdx.x * blockDim.x + threadIdx.x;
    if (e < E) atomicAdd(&g_cnt[dst[e]], 1);
}

// ---------------------------------------------------------------------------
// 3-phase exclusive scan over g_cnt -> g_rowstart (+ cursor, dinv)
// ---------------------------------------------------------------------------
__global__ __launch_bounds__(1024)
void k_scanA(int n) {
    __shared__ int sm[1024];
    int t = threadIdx.x;
    int i = blockIdx.x * 1024 + t;
    int v = (i < n) ? g_cnt[i] : 0;
    sm[t] = v;
    __syncthreads();
#pragma unroll
    for (int off = 1; off < 1024; off <<= 1) {
        int u = (t >= off) ? sm[t - off] : 0;
        __syncthreads();
        sm[t] += u;
        __syncthreads();
    }
    if (i < n) g_part[i] = sm[t] - v;          // exclusive
    if (t == 1023) g_bsum[blockIdx.x] = sm[t]; // block total
}

__global__ __launch_bounds__(128)
void k_scanB() {
    __shared__ int sm[128];
    int t = threadIdx.x;
    int v = (t < NB_SCAN) ? g_bsum[t] : 0;
    sm[t] = v;
    __syncthreads();
#pragma unroll
    for (int off = 1; off < 128; off <<= 1) {
        int u = (t >= off) ? sm[t - off] : 0;
        __syncthreads();
        sm[t] += u;
        __syncthreads();
    }
    g_boff[t] = sm[t] - v;                     // exclusive
}

__global__ void k_scanC(int n, int E) {
    int i = blockIdx.x * blockDim.x + threadIdx.x;
    if (i < n) {
        int rs = g_part[i] + g_boff[i >> 10];
        g_rowstart[i] = rs;
        g_cursor[i]   = rs;
        g_dinv[i]     = rsqrtf((float)(g_cnt[i] + 1));  // +1 self-loop
    }
    if (i == 0) g_rowstart[n] = E;
}

// ---------------------------------------------------------------------------
// Counting-sort fill: g_esrc grouped by dst
// ---------------------------------------------------------------------------
__global__ void k_fill(const int* __restrict__ src,
                       const int* __restrict__ dst, int E) {
    int e = blockIdx.x * blockDim.x + threadIdx.x;
    if (e < E) {
        int pos = atomicAdd(&g_cursor[dst[e]], 1);
        g_esrc[pos] = src[e];
    }
}

// ---------------------------------------------------------------------------
// FUSED gather + GEMM + epilogue.
// Phase 1: each of 8 warps gathers 8 rows (CSR, shfl-broadcast, self-loop
//          folded in) into agg[64][132] row-major (conflict-free writes).
// Phase 2: out_tile = agg @ W^T + b, PReLU. Ws tiles k-major (conflict-free
//          reads), KT=16 -> 42.2 KB static smem, 4 blocks/SM.
// L2-bound phase-1 blocks overlap with FFMA-bound phase-2 blocks chip-wide.
// ---------------------------------------------------------------------------
#define KT 16
#define WR 132

__global__ __launch_bounds__(256)
void k_fused(const float4* __restrict__ x4, const float* __restrict__ W,
             const float* __restrict__ b, const float* __restrict__ prelu_a,
             float* __restrict__ out, int n) {
    __shared__ float agg[64 * WR];   // [r][k], stride 132 (33.8 KB)
    __shared__ float Ws[KT * WR];    // [k][c]              (8.4 KB)

    int tid  = threadIdx.x;
    int lane = tid & 31;
    int warp = tid >> 5;
    int row0 = blockIdx.x * 64;

    // ---- Phase 1: gather ----
#pragma unroll 1
    for (int i = 0; i < 8; i++) {
        int r  = warp * 8 + i;
        int gr = row0 + r;
        float4 acc = make_float4(0.f, 0.f, 0.f, 0.f);
        if (gr < n) {
            float dd = g_dinv[gr];
            float sl = dd * dd;
            float4 xv = __ldg(&x4[gr * 32 + lane]);   // self-loop term
            acc.x = xv.x * sl; acc.y = xv.y * sl;
            acc.z = xv.z * sl; acc.w = xv.w * sl;

            int beg = g_rowstart[gr];
            int end = g_rowstart[gr + 1];
            for (int j0 = beg; j0 < end; j0 += 32) {
                int jn = min(32, end - j0);
                int   s  = 0;
                float ds = 0.f;
                if (lane < jn) {
                    s  = g_esrc[j0 + lane];
                    ds = g_dinv[s];
                }
#pragma unroll 4
                for (int t = 0; t < jn; t++) {
                    int   ss = __shfl_sync(0xffffffffu, s, t);
                    float nm = __shfl_sync(0xffffffffu, ds, t) * dd;
                    float4 v = __ldg(&x4[ss * 32 + lane]);
                    acc.x += v.x * nm;
                    acc.y += v.y * nm;
                    acc.z += v.z * nm;
                    acc.w += v.w * nm;
                }
            }
        }
        *(float4*)&agg[r * WR + lane * 4] = acc;   // conflict-free
    }
    __syncthreads();

    // ---- Phase 2: GEMM ----
    int tx = tid & 15, ty = tid >> 4;
    int r0 = ty * 4;
    int c0 = tx * 8;

    float acc[4][8];
#pragma unroll
    for (int i = 0; i < 4; i++)
#pragma unroll
        for (int j = 0; j < 8; j++) acc[i][j] = 0.f;

    for (int k0 = 0; k0 < 128; k0 += KT) {
        // Ws tile: 128 cols x 16 k = 512 float4 / 256 threads = 2 each,
        // stored transposed to k-major.
#pragma unroll
        for (int it = 0; it < 2; it++) {
            int i = tid + it * 256;          // 0..511
            int c = i >> 2, q = i & 3;       // q = k-quad within tile
            float4 v = ((const float4*)W)[c * 32 + (k0 >> 2) + q];
            Ws[(q * 4 + 0) * WR + c] = v.x;
            Ws[(q * 4 + 1) * WR + c] = v.y;
            Ws[(q * 4 + 2) * WR + c] = v.z;
            Ws[(q * 4 + 3) * WR + c] = v.w;
        }
        __syncthreads();

#pragma unroll
        for (int kk = 0; kk < KT; kk++) {
            float xr[4];
#pragma unroll
            for (int i = 0; i < 4; i++)
                xr[i] = agg[(r0 + i) * WR + k0 + kk];   // broadcast
            float4 w0 = *(const float4*)&Ws[kk * WR + c0];
            float4 w1 = *(const float4*)&Ws[kk * WR + c0 + 4];
            float wc[8] = {w0.x, w0.y, w0.z, w0.w, w1.x, w1.y, w1.z, w1.w};
#pragma unroll
            for (int i = 0; i < 4; i++)
#pragma unroll
                for (int j = 0; j < 8; j++)
                    acc[i][j] += xr[i] * wc[j];
        }
        __syncthreads();
    }

    // ---- Epilogue: bias + PReLU ----
    float a = prelu_a[0];
    float bb[8];
#pragma unroll
    for (int j = 0; j < 8; j++) bb[j] = b[c0 + j];

#pragma unroll
    for (int i = 0; i < 4; i++) {
        int r = row0 + r0 + i;
        if (r < n) {
            float vals[8];
#pragma unroll
            for (int j = 0; j < 8; j++) {
                float v = acc[i][j] + bb[j];
                vals[j] = v >= 0.f ? v : a * v;
            }
            float4* op = (float4*)out + r * 32 + (c0 >> 2);
            op[0] = make_float4(vals[0], vals[1], vals[2], vals[3]);
            op[1] = make_float4(vals[4], vals[5], vals[6], vals[7]);
        }
    }
}

// ---------------------------------------------------------------------------
extern "C" void kernel_launch(void* const* d_in, const int* in_sizes, int n_in,
                              void* d_out, int out_size) {
    const float* x  = (const float*)d_in[0];
    const int*   ei = (const int*)d_in[1];      // int32 (JAX x64 disabled)
    const float* W  = (const float*)d_in[2];
    const float* b  = (const float*)d_in[3];
    const float* pa = (const float*)d_in[4];
    float* out = (float*)d_out;

    int n = in_sizes[0] / H;          // 100000
    int E = in_sizes[1] / 2;          // 1600000
    if (E > EMAX) E = EMAX;
    const int* src = ei;
    const int* dst = ei + E;

    k_zero <<<(n + 255) / 256, 256>>>(n);
    k_deg  <<<(E + 255) / 256, 256>>>(dst, E);
    k_scanA<<<NB_SCAN, 1024>>>(n);
    k_scanB<<<1, 128>>>();
    k_scanC<<<(n + 255) / 256, 256>>>(n, E);
    k_fill <<<(E + 255) / 256, 256>>>(src, dst, E);
    k_fused<<<(n + 63) / 64, 256>>>((const float4*)x, W, b, pa, out, n);
}